// round 16
// baseline (speedup 1.0000x reference)
#include <cuda_runtime.h>
#include <cuda_fp16.h>
#include <math.h>
#include <cstdint>

// ---------------- scratch (static device globals; no allocation) ----------------
__device__ float g_adp[1024 * 1024];                                   //   4 MB
__device__ float g_MstackT[6144 * 1024];                               //  24 MB [slot*1024+w, v]
// B operand, tiled+swizzled: tile (nt,kt) = 128x64 fp16 (16KB), nt<8, kt<96
__device__ __align__(256) __half g_MTt[8 * 96 * 8192];                 //  12.6 MB
// A operand, tiled+swizzled: tile (mt,kt) = 128x64 fp16 (16KB), mt<192, kt<96
__device__ __align__(256) __half g_YfT[(size_t)192 * 96 * 8192];       // 301 MB
__device__ float g_Y0[(size_t)24576 * 1024];                           // 100 MB identity-term
__device__ float g_Or[(size_t)24576 * 1024];                           // 100 MB GEMM out

// ================= PTX helpers (baseline sm_90-class) ===========================
__device__ __forceinline__ uint32_t smem_u32(const void* p) {
    uint32_t a;
    asm("{ .reg .u64 t; cvta.to.shared.u64 t, %1; cvt.u32.u64 %0, t; }" : "=r"(a) : "l"(p));
    return a;
}
__device__ __forceinline__ void mbar_init(uint32_t a, uint32_t cnt) {
    asm volatile("mbarrier.init.shared.b64 [%0], %1;" :: "r"(a), "r"(cnt) : "memory");
}
__device__ __forceinline__ void mbar_expect_tx(uint32_t a, uint32_t bytes) {
    asm volatile("mbarrier.arrive.expect_tx.shared.b64 _, [%0], %1;"
                 :: "r"(a), "r"(bytes) : "memory");
}
__device__ __forceinline__ void mbar_wait(uint32_t a, uint32_t parity) {
    uint32_t done;
    asm volatile("{\n\t.reg .pred p;\n\t"
        "mbarrier.try_wait.parity.acquire.cta.shared::cta.b64 p, [%1], %2;\n\t"
        "selp.b32 %0, 1, 0, p;\n\t}" : "=r"(done) : "r"(a), "r"(parity) : "memory");
    while (!done) {
        asm volatile("{\n\t.reg .pred p;\n\t"
            "mbarrier.try_wait.parity.acquire.cta.shared::cta.b64 p, [%1], %2, 0x989680;\n\t"
            "selp.b32 %0, 1, 0, p;\n\t}" : "=r"(done) : "r"(a), "r"(parity) : "memory");
    }
}
__device__ __forceinline__ void bulk_g2s(uint32_t dst, const void* src, uint32_t bytes,
                                         uint32_t mbar) {
    asm volatile("cp.async.bulk.shared::cluster.global.mbarrier::complete_tx::bytes "
                 "[%0], [%1], %2, [%3];"
                 :: "r"(dst), "l"(src), "r"(bytes), "r"(mbar) : "memory");
}
__device__ __forceinline__ void ldsm_x4(uint32_t* r, uint32_t addr) {
    asm volatile("ldmatrix.sync.aligned.m8n8.x4.shared.b16 {%0,%1,%2,%3}, [%4];"
        : "=r"(r[0]), "=r"(r[1]), "=r"(r[2]), "=r"(r[3]) : "r"(addr));
}
// fp16-accumulate HMMA (full-rate): D(f16) = A*B + C(f16)
__device__ __forceinline__ void mma_h16_zero(uint32_t* d, const uint32_t* a,
                                             uint32_t b0, uint32_t b1) {
    asm volatile("mma.sync.aligned.m16n8k16.row.col.f16.f16.f16.f16 "
        "{%0,%1}, {%2,%3,%4,%5}, {%6,%7}, {%8,%9};"
        : "=r"(d[0]), "=r"(d[1])
        : "r"(a[0]), "r"(a[1]), "r"(a[2]), "r"(a[3]), "r"(b0), "r"(b1),
          "r"(0u), "r"(0u));
}
__device__ __forceinline__ void mma_h16(uint32_t* d, const uint32_t* a,
                                        uint32_t b0, uint32_t b1) {
    asm volatile("mma.sync.aligned.m16n8k16.row.col.f16.f16.f16.f16 "
        "{%0,%1}, {%2,%3,%4,%5}, {%6,%7}, {%0,%1};"
        : "+r"(d[0]), "+r"(d[1])
        : "r"(a[0]), "r"(a[1]), "r"(a[2]), "r"(a[3]), "r"(b0), "r"(b1));
}
__device__ __forceinline__ uint32_t swz128(uint32_t o) { return o ^ ((o >> 3) & 0x70); }

// ---------------- adaptive adjacency: softmax(relu(nv1 @ nv2), axis=1) ----------
__global__ void adp_kernel(const float* __restrict__ nv1, const float* __restrict__ nv2) {
    int v = blockIdx.x;
    int tid = threadIdx.x;
    __shared__ float e1[10];
    __shared__ float red[256];
    if (tid < 10) e1[tid] = nv1[v * 10 + tid];
    __syncthreads();

    float vals[4];
#pragma unroll
    for (int q = 0; q < 4; q++) {
        int w = tid + q * 256;
        float s = 0.f;
#pragma unroll
        for (int t = 0; t < 10; t++) s += e1[t] * nv2[t * 1024 + w];
        vals[q] = fmaxf(s, 0.f);
    }
    float m = fmaxf(fmaxf(vals[0], vals[1]), fmaxf(vals[2], vals[3]));
    red[tid] = m;
    __syncthreads();
    for (int s = 128; s > 0; s >>= 1) {
        if (tid < s) red[tid] = fmaxf(red[tid], red[tid + s]);
        __syncthreads();
    }
    m = red[0];
    __syncthreads();

    float e[4];
    float ssum = 0.f;
#pragma unroll
    for (int q = 0; q < 4; q++) { e[q] = expf(vals[q] - m); ssum += e[q]; }
    red[tid] = ssum;
    __syncthreads();
    for (int s = 128; s > 0; s >>= 1) {
        if (tid < s) red[tid] += red[tid + s];
        __syncthreads();
    }
    float denom = red[0];
#pragma unroll
    for (int q = 0; q < 4; q++) {
        int w = tid + q * 256;
        g_adp[v * 1024 + w] = e[q] / denom;
    }
}

// -------- transposed copy: MstackT[slot*1024+w][v] = M[v][w], slots 0,2,4 -------
__global__ void copy_slots_T(const float* __restrict__ A1, const float* __restrict__ A2) {
    __shared__ float ts[32][33];
    int which = blockIdx.z;
    const float* src = (which == 0) ? A1 : (which == 1) ? A2 : g_adp;
    int v0 = blockIdx.y * 32, w0 = blockIdx.x * 32;
    int tx = threadIdx.x, ty = threadIdx.y;  // 32 x 8
#pragma unroll
    for (int q = 0; q < 4; q++)
        ts[ty + q * 8][tx] = src[(size_t)(v0 + ty + q * 8) * 1024 + w0 + tx];
    __syncthreads();
    size_t base = ((size_t)(which * 2) * 1024 + w0) * 1024 + v0;
#pragma unroll
    for (int q = 0; q < 4; q++)
        g_MstackT[base + (size_t)(ty + q * 8) * 1024 + tx] = ts[tx][ty + q * 8];
}

// ---------------- generic 128x128x16 fp32 SGEMM body (squares only) -------------
__device__ __forceinline__ void sgemm_body(
    const float* __restrict__ A, const float* __restrict__ B, float* __restrict__ C,
    int K, int lda, int ldb, int ldc)
{
    __shared__ float As[2][16][132];
    __shared__ float Bs[2][16][128];

    const int tid = threadIdx.x;
    const int bm = blockIdx.y * 128;
    const int bn = blockIdx.x * 128;
    const int tx = tid & 15;
    const int ty = tid >> 4;
    const int a_row = tid >> 2;
    const int a_col = (tid & 3) << 2;
    const int b_row = tid >> 5;
    const int b_col = (tid & 31) << 2;

    const float* Aptr = A + (size_t)bm * lda;
    const float* Bptr = B + bn;

    float acc[8][8];
#pragma unroll
    for (int i = 0; i < 8; i++)
#pragma unroll
        for (int j = 0; j < 8; j++) acc[i][j] = 0.f;

    {
        float4 a0 = *(const float4*)(Aptr + (size_t)a_row * lda + a_col);
        float4 a1 = *(const float4*)(Aptr + (size_t)(a_row + 64) * lda + a_col);
        float4 b0 = *(const float4*)(Bptr + (size_t)b_row * ldb + b_col);
        float4 b1 = *(const float4*)(Bptr + (size_t)(b_row + 8) * ldb + b_col);
        As[0][a_col + 0][a_row] = a0.x; As[0][a_col + 1][a_row] = a0.y;
        As[0][a_col + 2][a_row] = a0.z; As[0][a_col + 3][a_row] = a0.w;
        As[0][a_col + 0][a_row + 64] = a1.x; As[0][a_col + 1][a_row + 64] = a1.y;
        As[0][a_col + 2][a_row + 64] = a1.z; As[0][a_col + 3][a_row + 64] = a1.w;
        *(float4*)&Bs[0][b_row][b_col] = b0;
        *(float4*)&Bs[0][b_row + 8][b_col] = b1;
    }
    __syncthreads();

    const int nt = K >> 4;
    for (int t = 0; t < nt; t++) {
        const int cur = t & 1;
        float4 a0, a1, b0, b1;
        if (t + 1 < nt) {
            int k0 = (t + 1) << 4;
            a0 = *(const float4*)(Aptr + (size_t)a_row * lda + k0 + a_col);
            a1 = *(const float4*)(Aptr + (size_t)(a_row + 64) * lda + k0 + a_col);
            b0 = *(const float4*)(Bptr + (size_t)(k0 + b_row) * ldb + b_col);
            b1 = *(const float4*)(Bptr + (size_t)(k0 + b_row + 8) * ldb + b_col);
        }
#pragma unroll
        for (int kk = 0; kk < 16; kk++) {
            float af[8], bf[8];
            *(float4*)(af)     = *(const float4*)&As[cur][kk][ty * 8];
            *(float4*)(af + 4) = *(const float4*)&As[cur][kk][ty * 8 + 4];
            *(float4*)(bf)     = *(const float4*)&Bs[cur][kk][tx * 8];
            *(float4*)(bf + 4) = *(const float4*)&Bs[cur][kk][tx * 8 + 4];
#pragma unroll
            for (int i = 0; i < 8; i++)
#pragma unroll
                for (int j = 0; j < 8; j++)
                    acc[i][j] = fmaf(af[i], bf[j], acc[i][j]);
        }
        if (t + 1 < nt) {
            const int nxt = cur ^ 1;
            As[nxt][a_col + 0][a_row] = a0.x; As[nxt][a_col + 1][a_row] = a0.y;
            As[nxt][a_col + 2][a_row] = a0.z; As[nxt][a_col + 3][a_row] = a0.w;
            As[nxt][a_col + 0][a_row + 64] = a1.x; As[nxt][a_col + 1][a_row + 64] = a1.y;
            As[nxt][a_col + 2][a_row + 64] = a1.z; As[nxt][a_col + 3][a_row + 64] = a1.w;
            *(float4*)&Bs[nxt][b_row][b_col] = b0;
            *(float4*)&Bs[nxt][b_row + 8][b_col] = b1;
        }
        __syncthreads();
    }

    float* Cp = C + (size_t)(bm + ty * 8) * ldc + bn + tx * 8;
#pragma unroll
    for (int i = 0; i < 8; i++) {
        *(float4*)(Cp + (size_t)i * ldc)     = make_float4(acc[i][0], acc[i][1], acc[i][2], acc[i][3]);
        *(float4*)(Cp + (size_t)i * ldc + 4) = make_float4(acc[i][4], acc[i][5], acc[i][6], acc[i][7]);
    }
}

// squares on transposed slots: (A^2)^T = A^T @ A^T; slots 0,2,4 -> 1,3,5
__global__ __launch_bounds__(256, 2) void squares_T_kernel() {
    int slot = blockIdx.z * 2;  // 0, 2, 4
    const float* src = g_MstackT + (size_t)slot * 1024 * 1024;
    float* dst = g_MstackT + (size_t)(slot + 1) * 1024 * 1024;
    sgemm_body(src, src, dst, 1024, 1024, 1024, 1024);
}

// MstackT [slot*1024+w, v] -> tiled+swizzled fp16 B operand g_MTt
// B logical [w, slot*1024+v]; tile (nt = w/128, kt = gk/64) of 128x64 (16KB)
__global__ void convert_mh() {
    int row = blockIdx.x;                 // slot*1024 + w
    int slot = row >> 10, w = row & 1023;
    const float* src = g_MstackT + (size_t)row * 1024;
    int nt = w >> 7, r = w & 127;
    char* base = (char*)g_MTt;
    for (int v = threadIdx.x; v < 1024; v += 256) {
        int gk = slot * 1024 + v;
        int kt = gk >> 6, kl = gk & 63;
        size_t byte = ((size_t)(nt * 96 + kt) << 14) + swz128((uint32_t)(r * 128 + kl * 2));
        *(__half*)(base + byte) = __float2half(src[v]);
    }
}

// ----- fused transpose + channel mix, reading x[n,c,v,l] directly ---------------
// grid (16 v-tiles of 64, 64 n), 384 threads (12 warps; warp = l).
// slot 0 -> g_Y0 fp32 [(n,l,o), v]; slots 1..6 -> g_YfT tiled+swizzled fp16.
static constexpr int CMX_SMEM = 32 * 780 * 4 + 32 * 224 * 4;   // 99840 + 28672 = 128512
__global__ __launch_bounds__(384) void chanmix_x(const float* __restrict__ x,
                                                 const float* __restrict__ W) {
    extern __shared__ float xs[];                 // [c][l*65 + v]  (32 x 780)
    float* Wf = xs + 32 * 780;                    // [o*224 + cc]   (7168)
    int v0 = blockIdx.x * 64;
    int n = blockIdx.y;
    int tid = threadIdx.x;
    int l = tid >> 5;            // warp id = l (0..11)
    int lane = tid & 31;

    for (int i = tid; i < 32 * 224; i += 384) Wf[i] = W[i];

    const float* xb = x + (size_t)n * 32 * 12288 + (size_t)v0 * 12;
    for (int i = tid; i < 24576; i += 384) {
        int c = i / 768, q = i - c * 768;
        int v = q / 12, ll = q - v * 12;
        xs[c * 780 + ll * 65 + v] = xb[(size_t)c * 12288 + q];
    }
    __syncthreads();

    float xv0[32], xv1[32];
#pragma unroll
    for (int c = 0; c < 32; c++) {
        xv0[c] = xs[c * 780 + l * 65 + lane];
        xv1[c] = xs[c * 780 + l * 65 + lane + 32];
    }

    size_t rowbase = (size_t)(n * 12 + l) * 32;
    char* ybase = (char*)g_YfT;

    for (int slot = 0; slot < 7; slot++) {
#pragma unroll 2
        for (int o = 0; o < 32; o++) {
            const float* wr = &Wf[o * 224 + slot * 32];
            float s0 = 0.f, s1 = 0.f;
#pragma unroll
            for (int c = 0; c < 32; c++) {
                s0 = fmaf(wr[c], xv0[c], s0);
                s1 = fmaf(wr[c], xv1[c], s1);
            }
            size_t row = rowbase + o;
            if (slot == 0) {
                g_Y0[row * 1024 + v0 + lane]      = s0;
                g_Y0[row * 1024 + v0 + lane + 32] = s1;
            } else {
                int gk = (slot - 1) * 1024 + v0;         // kl = lane / lane+32, same kt
                int kt = gk >> 6;
                int mt = (int)(row >> 7), r = (int)(row & 127);
                size_t tb = ((size_t)(mt * 96 + kt) << 14);
                *(__half*)(ybase + tb + swz128((uint32_t)(r * 128 + lane * 2)))        = __float2half(s0);
                *(__half*)(ybase + tb + swz128((uint32_t)(r * 128 + (lane + 32) * 2))) = __float2half(s1);
            }
        }
    }
}

// ===== main GEMM: Or = Yf @ MT^T; fp16-acc windows (64 k) + fp32 spill ==========
// CTA 128x128, 256 threads (8 warps, warp tile 64x32), 2 CTAs/SM, bulk 3-stage.
static constexpr int K_ITERS = 96;
static constexpr int STG = 32768;                  // A 16K | B 16K
static constexpr int GEMM_SMEM = 3 * STG + 32;     // 98336 (x2 CTAs <= 228KB)

__global__ __launch_bounds__(256, 2) void gemm_bulk() {
    extern __shared__ char smem[];
    const uint32_t sb = smem_u32(smem);
    const uint32_t sbar = sb + 3 * STG;
    const int tid = threadIdx.x;
    const int warp = tid >> 5, lane = tid & 31;
    const int mt = blockIdx.y;                     // 192
    const int ntb = blockIdx.x;                    // 8
    const int bm = mt * 128;
    const int bn = ntb * 128;
    const int wm = (warp >> 2) * 64;               // 0 / 64
    const int wn = (warp & 3) * 32;                // 0..96

    const char* Abase = (const char*)g_YfT + ((size_t)mt * 96) * 16384;
    const char* Bbase = (const char*)g_MTt + ((size_t)ntb * 96) * 16384;

    if (tid == 0) {
#pragma unroll
        for (int s = 0; s < 3; s++) mbar_init(sbar + 8 * s, 1);
    }
    __syncthreads();

    auto issue = [&](int t) {
        int s = t % 3;
        uint32_t bar = sbar + 8 * s;
        mbar_expect_tx(bar, 32768);
        bulk_g2s(sb + s * STG,         Abase + (size_t)t * 16384, 16384, bar);
        bulk_g2s(sb + s * STG + 16384, Bbase + (size_t)t * 16384, 16384, bar);
    };
    if (tid == 0) { issue(0); issue(1); issue(2); }

    float acc[4][4][4];
#pragma unroll
    for (int mi = 0; mi < 4; mi++)
#pragma unroll
        for (int ni = 0; ni < 4; ni++)
#pragma unroll
            for (int q = 0; q < 4; q++) acc[mi][ni][q] = 0.f;

    const int lrow = lane & 15, lch = (lane >> 4) * 16;

    for (int t = 0; t < K_ITERS; t++) {
        const int s = t % 3;
        mbar_wait(sbar + 8 * s, (t / 3) & 1);

        const uint32_t ab = sb + (uint32_t)s * STG;
        const uint32_t bb = ab + 16384;

        uint32_t ch[4][4][2];   // fp16 window accumulators (one k-tile = 64 terms)
#pragma unroll
        for (int kk = 0; kk < 4; kk++) {
            uint32_t b[2][4];
#pragma unroll
            for (int nj = 0; nj < 2; nj++)
                ldsm_x4(b[nj], bb + swz128((uint32_t)((wn + nj * 16 + lrow) * 128 + kk * 32 + lch)));
#pragma unroll
            for (int mi = 0; mi < 4; mi++) {
                uint32_t a[4];
                ldsm_x4(a, ab + swz128((uint32_t)((wm + mi * 16 + lrow) * 128 + kk * 32 + lch)));
#pragma unroll
                for (int ni = 0; ni < 4; ni++) {
                    if (kk == 0)
                        mma_h16_zero(ch[mi][ni], a, b[ni >> 1][ni & 1], b[ni >> 1][(ni & 1) + 2]);
                    else
                        mma_h16(ch[mi][ni], a, b[ni >> 1][ni & 1], b[ni >> 1][(ni & 1) + 2]);
                }
            }
        }
        // spill fp16 window into fp32 accumulators
#pragma unroll
        for (int mi = 0; mi < 4; mi++)
#pragma unroll
            for (int ni = 0; ni < 4; ni++) {
                float2 f0 = __half22float2(*reinterpret_cast<__half2*>(&ch[mi][ni][0]));
                float2 f1 = __half22float2(*reinterpret_cast<__half2*>(&ch[mi][ni][1]));
                acc[mi][ni][0] += f0.x; acc[mi][ni][1] += f0.y;
                acc[mi][ni][2] += f1.x; acc[mi][ni][3] += f1.y;
            }
        __syncthreads();
        if (tid == 0 && t + 3 < K_ITERS) issue(t + 3);
    }

    // writeback to g_Or (ld = 1024)
    const int crow = lane >> 2, ccol = (lane & 3) * 2;
#pragma unroll
    for (int mi = 0; mi < 4; mi++) {
#pragma unroll
        for (int ni = 0; ni < 4; ni++) {
            float* zp = g_Or + (size_t)(bm + wm + mi * 16 + crow) * 1024 + bn + wn + ni * 8 + ccol;
            *(float2*)zp = make_float2(acc[mi][ni][0], acc[mi][ni][1]);
            *(float2*)(zp + (size_t)8 * 1024) = make_float2(acc[mi][ni][2], acc[mi][ni][3]);
        }
    }
}

// ------ final: out[n,o,w,l] = bias[o] + Y0[(n,l,o),w] + Or[(n,l,o),w] -----------
__global__ __launch_bounds__(256) void final_kernel(const float* __restrict__ bias,
                                                    float* __restrict__ out) {
    __shared__ float s[12][260];
    int v0 = blockIdx.x * 256;   // 4
    int o = blockIdx.y;          // 32
    int n = blockIdx.z;          // 64
    int tid = threadIdx.x;
    float bo = bias[o];
#pragma unroll
    for (int l = 0; l < 12; l++) {
        size_t row = (size_t)(n * 12 + l) * 32 + o;
        s[l][tid] = g_Or[row * 1024 + v0 + tid] + g_Y0[row * 1024 + v0 + tid] + bo;
    }
    __syncthreads();
    size_t ob = ((size_t)(n * 32 + o) * 1024 + v0) * 12;
    for (int i = tid; i < 3072; i += 256) {
        int v = i / 12, l = i - v * 12;
        out[ob + i] = s[l][v];
    }
}

// -------------------------------- launch ----------------------------------------
extern "C" void kernel_launch(void* const* d_in, const int* in_sizes, int n_in,
                              void* d_out, int out_size) {
    const float* x   = (const float*)d_in[0];
    const float* A1  = (const float*)d_in[1];
    const float* A2  = (const float*)d_in[2];
    const float* nv1 = (const float*)d_in[3];
    const float* nv2 = (const float*)d_in[4];
    const float* W   = (const float*)d_in[5];
    const float* b   = (const float*)d_in[6];
    float* out = (float*)d_out;

    cudaFuncSetAttribute(gemm_bulk, cudaFuncAttributeMaxDynamicSharedMemorySize, GEMM_SMEM);
    cudaFuncSetAttribute(chanmix_x, cudaFuncAttributeMaxDynamicSharedMemorySize, CMX_SMEM);

    adp_kernel<<<1024, 256>>>(nv1, nv2);
    copy_slots_T<<<dim3(32, 32, 3), dim3(32, 8)>>>(A1, A2);
    squares_T_kernel<<<dim3(8, 8, 3), 256>>>();
    convert_mh<<<6144, 256>>>();
    chanmix_x<<<dim3(16, 64), 384, CMX_SMEM>>>(x, W);
    gemm_bulk<<<dim3(8, 192), 256, GEMM_SMEM>>>();
    final_kernel<<<dim3(4, 32, 64), 256>>>(b, out);
}

// round 17
// speedup vs baseline: 1.2753x; 1.2753x over previous
#include <cuda_runtime.h>
#include <cuda_fp16.h>
#include <math.h>
#include <cstdint>

// ---------------- scratch (static device globals; no allocation) ----------------
__device__ float g_adp[1024 * 1024];                                   //   4 MB
// B operand of main GEMM, tiled+swizzled: tile (nt,kt) = 128x64 fp16 (16KB), nt<8, kt<96
__device__ __align__(256) __half g_MTt[8 * 96 * 8192];                 //  12.6 MB
// square-GEMM operands (fp16, tiled 128x64, mt<8, kt<16 per matrix)
__device__ __align__(256) __half g_SqA[3 * 1024 * 1024];               //   6 MB  (A^T)
__device__ __align__(256) __half g_SqB[3 * 1024 * 1024];               //   6 MB  (A direct)
// A operand of main GEMM, tiled+swizzled: tile (mt,kt) = 128x64 fp16 (16KB), mt<192, kt<96
__device__ __align__(256) __half g_YfT[(size_t)192 * 96 * 8192];       // 301 MB
__device__ float g_Y0[(size_t)24576 * 1024];                           // 100 MB identity-term
__device__ float g_Or[(size_t)24576 * 1024];                           // 100 MB GEMM out

// ================= PTX helpers (baseline sm_90-class) ===========================
__device__ __forceinline__ uint32_t smem_u32(const void* p) {
    uint32_t a;
    asm("{ .reg .u64 t; cvta.to.shared.u64 t, %1; cvt.u32.u64 %0, t; }" : "=r"(a) : "l"(p));
    return a;
}
__device__ __forceinline__ void mbar_init(uint32_t a, uint32_t cnt) {
    asm volatile("mbarrier.init.shared.b64 [%0], %1;" :: "r"(a), "r"(cnt) : "memory");
}
__device__ __forceinline__ void mbar_expect_tx(uint32_t a, uint32_t bytes) {
    asm volatile("mbarrier.arrive.expect_tx.shared.b64 _, [%0], %1;"
                 :: "r"(a), "r"(bytes) : "memory");
}
__device__ __forceinline__ void mbar_wait(uint32_t a, uint32_t parity) {
    uint32_t done;
    asm volatile("{\n\t.reg .pred p;\n\t"
        "mbarrier.try_wait.parity.acquire.cta.shared::cta.b64 p, [%1], %2;\n\t"
        "selp.b32 %0, 1, 0, p;\n\t}" : "=r"(done) : "r"(a), "r"(parity) : "memory");
    while (!done) {
        asm volatile("{\n\t.reg .pred p;\n\t"
            "mbarrier.try_wait.parity.acquire.cta.shared::cta.b64 p, [%1], %2, 0x989680;\n\t"
            "selp.b32 %0, 1, 0, p;\n\t}" : "=r"(done) : "r"(a), "r"(parity) : "memory");
    }
}
__device__ __forceinline__ void bulk_g2s(uint32_t dst, const void* src, uint32_t bytes,
                                         uint32_t mbar) {
    asm volatile("cp.async.bulk.shared::cluster.global.mbarrier::complete_tx::bytes "
                 "[%0], [%1], %2, [%3];"
                 :: "r"(dst), "l"(src), "r"(bytes), "r"(mbar) : "memory");
}
__device__ __forceinline__ void ldsm_x4(uint32_t* r, uint32_t addr) {
    asm volatile("ldmatrix.sync.aligned.m8n8.x4.shared.b16 {%0,%1,%2,%3}, [%4];"
        : "=r"(r[0]), "=r"(r[1]), "=r"(r[2]), "=r"(r[3]) : "r"(addr));
}
__device__ __forceinline__ void mma_16816_f16(float* c, const uint32_t* a, uint32_t b0, uint32_t b1) {
    asm volatile("mma.sync.aligned.m16n8k16.row.col.f32.f16.f16.f32 "
        "{%0,%1,%2,%3}, {%4,%5,%6,%7}, {%8,%9}, {%0,%1,%2,%3};"
        : "+f"(c[0]), "+f"(c[1]), "+f"(c[2]), "+f"(c[3])
        : "r"(a[0]), "r"(a[1]), "r"(a[2]), "r"(a[3]), "r"(b0), "r"(b1));
}
__device__ __forceinline__ uint32_t swz128(uint32_t o) { return o ^ ((o >> 3) & 0x70); }

// ---------------- adaptive adjacency: softmax(relu(nv1 @ nv2), axis=1) ----------
__global__ void adp_kernel(const float* __restrict__ nv1, const float* __restrict__ nv2) {
    int v = blockIdx.x;
    int tid = threadIdx.x;
    __shared__ float e1[10];
    __shared__ float red[256];
    if (tid < 10) e1[tid] = nv1[v * 10 + tid];
    __syncthreads();

    float vals[4];
#pragma unroll
    for (int q = 0; q < 4; q++) {
        int w = tid + q * 256;
        float s = 0.f;
#pragma unroll
        for (int t = 0; t < 10; t++) s += e1[t] * nv2[t * 1024 + w];
        vals[q] = fmaxf(s, 0.f);
    }
    float m = fmaxf(fmaxf(vals[0], vals[1]), fmaxf(vals[2], vals[3]));
    red[tid] = m;
    __syncthreads();
    for (int s = 128; s > 0; s >>= 1) {
        if (tid < s) red[tid] = fmaxf(red[tid], red[tid + s]);
        __syncthreads();
    }
    m = red[0];
    __syncthreads();

    float e[4];
    float ssum = 0.f;
#pragma unroll
    for (int q = 0; q < 4; q++) { e[q] = expf(vals[q] - m); ssum += e[q]; }
    red[tid] = ssum;
    __syncthreads();
    for (int s = 128; s > 0; s >>= 1) {
        if (tid < s) red[tid] += red[tid + s];
        __syncthreads();
    }
    float denom = red[0];
#pragma unroll
    for (int q = 0; q < 4; q++) {
        int w = tid + q * 256;
        g_adp[v * 1024 + w] = e[q] / denom;
    }
}

// ---- prep: from A (1024x1024 fp32) build fp16 operands --------------------------
// (i)  g_SqB[which][n=v, t=w] = A[v,w]            (direct,   tiled 128x64)
// (ii) g_SqA[which][m=w, t=v] = A[v,w]            (transpose, tiled 128x64)
// (iii)g_MTt slot 2*which:  [w, gk=slot*1024+v] = A[v,w]   (transpose, main-B tiles)
// grid (32 wt, 32 vt, 3), 256 threads (8 warps).
__global__ void prep_m(const float* __restrict__ A1, const float* __restrict__ A2) {
    __shared__ float ts[32][33];
    int which = blockIdx.z;
    const float* src = (which == 0) ? A1 : (which == 1) ? A2 : g_adp;
    int v0 = blockIdx.y * 32, w0 = blockIdx.x * 32;
    int tid = threadIdx.x;
    int warp = tid >> 5, lane = tid & 31;

    // stage 32x32 tile (coalesced over w)
#pragma unroll
    for (int q = 0; q < 4; q++) {
        int vr = warp + q * 8;
        ts[vr][lane] = src[(size_t)(v0 + vr) * 1024 + w0 + lane];
    }
    __syncthreads();

    char* sqb = (char*)g_SqB + (size_t)which * 2097152;
    char* sqa = (char*)g_SqA + (size_t)which * 2097152;
    char* mtt = (char*)g_MTt;
    int slot = which * 2;

    // direct writes: warp handles v-rows, lane = w
#pragma unroll
    for (int q = 0; q < 4; q++) {
        int v = v0 + warp + q * 8;
        int w = w0 + lane;
        __half h = __float2half(ts[warp + q * 8][lane]);
        size_t byte = ((size_t)((v >> 7) * 16 + (w >> 6)) << 14)
                    + swz128((uint32_t)((v & 127) * 128 + (w & 63) * 2));
        *(__half*)(sqb + byte) = h;
    }
    // transposed writes: warp handles w-rows, lane = v
#pragma unroll
    for (int q = 0; q < 4; q++) {
        int w = w0 + warp + q * 8;
        int v = v0 + lane;
        __half h = __float2half(ts[lane][warp + q * 8]);
        size_t byteA = ((size_t)((w >> 7) * 16 + (v >> 6)) << 14)
                     + swz128((uint32_t)((w & 127) * 128 + (v & 63) * 2));
        *(__half*)(sqa + byteA) = h;
        int gk = slot * 1024 + v;
        size_t byteM = ((size_t)((w >> 7) * 96 + (gk >> 6)) << 14)
                     + swz128((uint32_t)((w & 127) * 128 + (gk & 63) * 2));
        *(__half*)(mtt + byteM) = h;
    }
}

// ---- squares via fp16 mma: D = SqA @ SqB^T = (A^2)^T, written into g_MTt slot 2w+1
// CTA 128x128, 256 threads, 3-stage bulk pipeline, K=1024 (16 k-tiles).
static constexpr int SQ_STG = 32768;
static constexpr int SQ_SMEM = 3 * SQ_STG + 32;

__global__ __launch_bounds__(256, 2) void squares16() {
    extern __shared__ char smem[];
    const uint32_t sb = smem_u32(smem);
    const uint32_t sbar = sb + 3 * SQ_STG;
    const int tid = threadIdx.x;
    const int warp = tid >> 5, lane = tid & 31;
    const int which = blockIdx.z;
    const int mt = blockIdx.y;                     // 8 (w tiles)
    const int ntb = blockIdx.x;                    // 8 (v tiles)
    const int bm = mt * 128;
    const int bn = ntb * 128;
    const int wm = (warp >> 2) * 64;
    const int wn = (warp & 3) * 32;

    const char* Abase = (const char*)g_SqA + (size_t)which * 2097152 + ((size_t)mt * 16) * 16384;
    const char* Bbase = (const char*)g_SqB + (size_t)which * 2097152 + ((size_t)ntb * 16) * 16384;

    if (tid == 0) {
#pragma unroll
        for (int s = 0; s < 3; s++) mbar_init(sbar + 8 * s, 1);
    }
    __syncthreads();

    auto issue = [&](int t) {
        int s = t % 3;
        uint32_t bar = sbar + 8 * s;
        mbar_expect_tx(bar, 32768);
        bulk_g2s(sb + s * SQ_STG,         Abase + (size_t)t * 16384, 16384, bar);
        bulk_g2s(sb + s * SQ_STG + 16384, Bbase + (size_t)t * 16384, 16384, bar);
    };
    if (tid == 0) { issue(0); issue(1); issue(2); }

    float acc[4][4][4];
#pragma unroll
    for (int mi = 0; mi < 4; mi++)
#pragma unroll
        for (int ni = 0; ni < 4; ni++)
#pragma unroll
            for (int q = 0; q < 4; q++) acc[mi][ni][q] = 0.f;

    const int lrow = lane & 15, lch = (lane >> 4) * 16;

    for (int t = 0; t < 16; t++) {
        const int s = t % 3;
        mbar_wait(sbar + 8 * s, (t / 3) & 1);
        const uint32_t ab = sb + (uint32_t)s * SQ_STG;
        const uint32_t bb = ab + 16384;
#pragma unroll
        for (int kk = 0; kk < 4; kk++) {
            uint32_t b[2][4];
#pragma unroll
            for (int nj = 0; nj < 2; nj++)
                ldsm_x4(b[nj], bb + swz128((uint32_t)((wn + nj * 16 + lrow) * 128 + kk * 32 + lch)));
#pragma unroll
            for (int mi = 0; mi < 4; mi++) {
                uint32_t a[4];
                ldsm_x4(a, ab + swz128((uint32_t)((wm + mi * 16 + lrow) * 128 + kk * 32 + lch)));
#pragma unroll
                for (int ni = 0; ni < 4; ni++)
                    mma_16816_f16(acc[mi][ni], a, b[ni >> 1][ni & 1], b[ni >> 1][(ni & 1) + 2]);
            }
        }
        __syncthreads();
        if (tid == 0 && t + 3 < 16) issue(t + 3);
    }

    // epilogue: write fp16 into g_MTt slot 2*which+1, tiled+swizzled
    const int crow = lane >> 2, ccol = (lane & 3) * 2;
    char* mtt = (char*)g_MTt;
    const int gkb = (which * 2 + 1) * 1024;
#pragma unroll
    for (int mi = 0; mi < 4; mi++) {
#pragma unroll
        for (int ni = 0; ni < 4; ni++) {
            int gm0 = bm + wm + mi * 16 + crow;
            int gv = bn + wn + ni * 8 + ccol;
            int gk = gkb + gv;
            __half2 h0 = __floats2half2_rn(acc[mi][ni][0], acc[mi][ni][1]);
            __half2 h1 = __floats2half2_rn(acc[mi][ni][2], acc[mi][ni][3]);
            size_t b0 = ((size_t)((gm0 >> 7) * 96 + (gk >> 6)) << 14)
                      + swz128((uint32_t)((gm0 & 127) * 128 + (gk & 63) * 2));
            int gm1 = gm0 + 8;
            size_t b1 = ((size_t)((gm1 >> 7) * 96 + (gk >> 6)) << 14)
                      + swz128((uint32_t)((gm1 & 127) * 128 + (gk & 63) * 2));
            *(__half2*)(mtt + b0) = h0;
            *(__half2*)(mtt + b1) = h1;
        }
    }
}

// ----- fused transpose + channel mix, reading x[n,c,v,l] directly ---------------
// grid (16 v-tiles of 64, 64 n), 384 threads (12 warps; warp = l).
// slot 0 -> g_Y0 fp32 [(n,l,o), v]; slots 1..6 -> g_YfT tiled+swizzled fp16.
static constexpr int CMX_SMEM = 32 * 780 * 4 + 32 * 224 * 4;   // 128512
__global__ __launch_bounds__(384) void chanmix_x(const float* __restrict__ x,
                                                 const float* __restrict__ W) {
    extern __shared__ float xs[];                 // [c][l*65 + v]  (32 x 780)
    float* Wf = xs + 32 * 780;                    // [o*224 + cc]
    int v0 = blockIdx.x * 64;
    int n = blockIdx.y;
    int tid = threadIdx.x;
    int l = tid >> 5;
    int lane = tid & 31;

    for (int i = tid; i < 32 * 224; i += 384) Wf[i] = W[i];

    const float* xb = x + (size_t)n * 32 * 12288 + (size_t)v0 * 12;
    for (int i = tid; i < 24576; i += 384) {
        int c = i / 768, q = i - c * 768;
        int v = q / 12, ll = q - v * 12;
        xs[c * 780 + ll * 65 + v] = xb[(size_t)c * 12288 + q];
    }
    __syncthreads();

    float xv0[32], xv1[32];
#pragma unroll
    for (int c = 0; c < 32; c++) {
        xv0[c] = xs[c * 780 + l * 65 + lane];
        xv1[c] = xs[c * 780 + l * 65 + lane + 32];
    }

    size_t rowbase = (size_t)(n * 12 + l) * 32;
    char* ybase = (char*)g_YfT;

    for (int slot = 0; slot < 7; slot++) {
#pragma unroll 2
        for (int o = 0; o < 32; o++) {
            const float* wr = &Wf[o * 224 + slot * 32];
            float s0 = 0.f, s1 = 0.f;
#pragma unroll
            for (int c = 0; c < 32; c++) {
                s0 = fmaf(wr[c], xv0[c], s0);
                s1 = fmaf(wr[c], xv1[c], s1);
            }
            size_t row = rowbase + o;
            if (slot == 0) {
                g_Y0[row * 1024 + v0 + lane]      = s0;
                g_Y0[row * 1024 + v0 + lane + 32] = s1;
            } else {
                int gk = (slot - 1) * 1024 + v0;
                int kt = gk >> 6;
                int mt = (int)(row >> 7), r = (int)(row & 127);
                size_t tb = ((size_t)(mt * 96 + kt) << 14);
                *(__half*)(ybase + tb + swz128((uint32_t)(r * 128 + lane * 2)))        = __float2half(s0);
                *(__half*)(ybase + tb + swz128((uint32_t)(r * 128 + (lane + 32) * 2))) = __float2half(s1);
            }
        }
    }
}

// ===== main GEMM: Or = Yf @ MT^T; fp16 in / fp32 acc, 2 CTAs/SM, bulk 3-stage ====
static constexpr int K_ITERS = 96;
static constexpr int STG = 32768;                  // A 16K | B 16K
static constexpr int GEMM_SMEM = 3 * STG + 32;

__global__ __launch_bounds__(256, 2) void gemm_bulk() {
    extern __shared__ char smem[];
    const uint32_t sb = smem_u32(smem);
    const uint32_t sbar = sb + 3 * STG;
    const int tid = threadIdx.x;
    const int warp = tid >> 5, lane = tid & 31;
    const int mt = blockIdx.y;                     // 192
    const int ntb = blockIdx.x;                    // 8
    const int bm = mt * 128;
    const int bn = ntb * 128;
    const int wm = (warp >> 2) * 64;
    const int wn = (warp & 3) * 32;

    const char* Abase = (const char*)g_YfT + ((size_t)mt * 96) * 16384;
    const char* Bbase = (const char*)g_MTt + ((size_t)ntb * 96) * 16384;

    if (tid == 0) {
#pragma unroll
        for (int s = 0; s < 3; s++) mbar_init(sbar + 8 * s, 1);
    }
    __syncthreads();

    auto issue = [&](int t) {
        int s = t % 3;
        uint32_t bar = sbar + 8 * s;
        mbar_expect_tx(bar, 32768);
        bulk_g2s(sb + s * STG,         Abase + (size_t)t * 16384, 16384, bar);
        bulk_g2s(sb + s * STG + 16384, Bbase + (size_t)t * 16384, 16384, bar);
    };
    if (tid == 0) { issue(0); issue(1); issue(2); }

    float acc[4][4][4];
#pragma unroll
    for (int mi = 0; mi < 4; mi++)
#pragma unroll
        for (int ni = 0; ni < 4; ni++)
#pragma unroll
            for (int q = 0; q < 4; q++) acc[mi][ni][q] = 0.f;

    const int lrow = lane & 15, lch = (lane >> 4) * 16;

    for (int t = 0; t < K_ITERS; t++) {
        const int s = t % 3;
        mbar_wait(sbar + 8 * s, (t / 3) & 1);

        const uint32_t ab = sb + (uint32_t)s * STG;
        const uint32_t bb = ab + 16384;

#pragma unroll
        for (int kk = 0; kk < 4; kk++) {
            uint32_t b[2][4];
#pragma unroll
            for (int nj = 0; nj < 2; nj++)
                ldsm_x4(b[nj], bb + swz128((uint32_t)((wn + nj * 16 + lrow) * 128 + kk * 32 + lch)));
#pragma unroll
            for (int mi = 0; mi < 4; mi++) {
                uint32_t a[4];
                ldsm_x4(a, ab + swz128((uint32_t)((wm + mi * 16 + lrow) * 128 + kk * 32 + lch)));
#pragma unroll
                for (int ni = 0; ni < 4; ni++)
                    mma_16816_f16(acc[mi][ni], a, b[ni >> 1][ni & 1], b[ni >> 1][(ni & 1) + 2]);
            }
        }
        __syncthreads();
        if (tid == 0 && t + 3 < K_ITERS) issue(t + 3);
    }

    // writeback to g_Or (ld = 1024)
    const int crow = lane >> 2, ccol = (lane & 3) * 2;
#pragma unroll
    for (int mi = 0; mi < 4; mi++) {
#pragma unroll
        for (int ni = 0; ni < 4; ni++) {
            float* zp = g_Or + (size_t)(bm + wm + mi * 16 + crow) * 1024 + bn + wn + ni * 8 + ccol;
            *(float2*)zp = make_float2(acc[mi][ni][0], acc[mi][ni][1]);
            *(float2*)(zp + (size_t)8 * 1024) = make_float2(acc[mi][ni][2], acc[mi][ni][3]);
        }
    }
}

// ------ final: out[n,o,w,l] = bias[o] + Y0[(n,l,o),w] + Or[(n,l,o),w] -----------
__global__ __launch_bounds__(256) void final_kernel(const float* __restrict__ bias,
                                                    float* __restrict__ out) {
    __shared__ float s[12][260];
    int v0 = blockIdx.x * 256;   // 4
    int o = blockIdx.y;          // 32
    int n = blockIdx.z;          // 64
    int tid = threadIdx.x;
    float bo = bias[o];
#pragma unroll
    for (int l = 0; l < 12; l++) {
        size_t row = (size_t)(n * 12 + l) * 32 + o;
        s[l][tid] = g_Or[row * 1024 + v0 + tid] + g_Y0[row * 1024 + v0 + tid] + bo;
    }
    __syncthreads();
    size_t ob = ((size_t)(n * 32 + o) * 1024 + v0) * 12;
    for (int i = tid; i < 3072; i += 256) {
        int v = i / 12, l = i - v * 12;
        out[ob + i] = s[l][v];
    }
}

// -------------------------------- launch ----------------------------------------
extern "C" void kernel_launch(void* const* d_in, const int* in_sizes, int n_in,
                              void* d_out, int out_size) {
    const float* x   = (const float*)d_in[0];
    const float* A1  = (const float*)d_in[1];
    const float* A2  = (const float*)d_in[2];
    const float* nv1 = (const float*)d_in[3];
    const float* nv2 = (const float*)d_in[4];
    const float* W   = (const float*)d_in[5];
    const float* b   = (const float*)d_in[6];
    float* out = (float*)d_out;

    cudaFuncSetAttribute(gemm_bulk, cudaFuncAttributeMaxDynamicSharedMemorySize, GEMM_SMEM);
    cudaFuncSetAttribute(squares16, cudaFuncAttributeMaxDynamicSharedMemorySize, SQ_SMEM);
    cudaFuncSetAttribute(chanmix_x, cudaFuncAttributeMaxDynamicSharedMemorySize, CMX_SMEM);

    adp_kernel<<<1024, 256>>>(nv1, nv2);
    prep_m<<<dim3(32, 32, 3), 256>>>(A1, A2);
    squares16<<<dim3(8, 8, 3), 256, SQ_SMEM>>>();
    chanmix_x<<<dim3(16, 64), 384, CMX_SMEM>>>(x, W);
    gemm_bulk<<<dim3(8, 192), 256, GEMM_SMEM>>>();
    final_kernel<<<dim3(4, 32, 64), 256>>>(b, out);
}